// round 14
// baseline (speedup 1.0000x reference)
#include <cuda_runtime.h>
#include <cstdint>

// ============================================================================
// VAE_Decoder_6030134084248 : 4-layer QKeras-quantized MLP (exact-integer form)
// Warp-specialized hybrid GEMM, issue-balanced split: warps 0-3 mma.sync on
// 80 cols (64x40 warp tiles), warps 4-7 dp4a on 48 cols. r10 chassis:
// 4-stage cp.async, 16KB/stage, one barrier per K-iter, 2 CTA/SM.
// ============================================================================

static const int M = 8192;

// ---- scratch (device globals: no allocation allowed) ----
__device__ __align__(128) float   g_w0q[128 * 1024];
__device__ __align__(128) int8_t  g_w1t[2048l * 1024];   // [N][K] signed codes
__device__ __align__(128) int8_t  g_w2t[4096l * 2048];
__device__ __align__(128) int8_t  g_w3t[4096l * 4096];
__device__ int     g_b0q[1024];
__device__ int     g_b1q[2048];
__device__ int     g_b2q[4096];
__device__ float   g_b3q[4096];
__device__ __align__(128) uint8_t g_a0[8192l * 1024];
__device__ __align__(128) uint8_t g_a1[8192l * 2048];
__device__ __align__(128) uint8_t g_a2[8192l * 4096];

__device__ __forceinline__ float qcode(float x) {
    float c = rintf(x * 32.0f);
    return fminf(fmaxf(c, -32.0f), 31.0f);
}

// ---- fused small quantizers (1 launch) -----------------------------------
__global__ void k_quant_small(const float* __restrict__ W0, float* __restrict__ w0q,
                              const float* __restrict__ b0, int* __restrict__ b0q,
                              const float* __restrict__ b1, int* __restrict__ b1q,
                              const float* __restrict__ b2, int* __restrict__ b2q,
                              const float* __restrict__ b3, float* __restrict__ b3q) {
    int b = blockIdx.x, t = threadIdx.x;
    if (b < 512)      { int i = b * 256 + t;        w0q[i] = qcode(W0[i]) * (1.0f / 32.0f); }
    else if (b < 516) { int i = (b - 512) * 256 + t; b0q[i] = (int)qcode(b0[i]); }
    else if (b < 524) { int i = (b - 516) * 256 + t; b1q[i] = (int)qcode(b1[i]); }
    else if (b < 540) { int i = (b - 524) * 256 + t; b2q[i] = (int)qcode(b2[i]); }
    else              { int i = (b - 540) * 256 + t; b3q[i] = qcode(b3[i]) * (1.0f / 32.0f); }
}

// ---- fused transpose-quant for W1/W2/W3 (1 launch) -----------------------
__global__ void k_quant_wT_all(const float* __restrict__ W1, int8_t* __restrict__ B1,
                               const float* __restrict__ W2, int8_t* __restrict__ B2,
                               const float* __restrict__ W3, int8_t* __restrict__ B3) {
    __shared__ int8_t t[32][33];
    int b = blockIdx.x;
    const float* W; int8_t* Bt; int K, N;
    if (b < 2048)       { W = W1; Bt = B1; K = 1024; N = 2048; }
    else if (b < 10240) { b -= 2048;  W = W2; Bt = B2; K = 2048; N = 4096; }
    else                { b -= 10240; W = W3; Bt = B3; K = 4096; N = 4096; }
    int nb = N / 32;
    int n0 = (b % nb) * 32, k0 = (b / nb) * 32;
    int tx = threadIdx.x, ty = threadIdx.y;   // 32 x 8
#pragma unroll
    for (int r = ty; r < 32; r += 8)
        t[r][tx] = (int8_t)qcode(W[(size_t)(k0 + r) * N + n0 + tx]);
    __syncthreads();
#pragma unroll
    for (int r = ty; r < 32; r += 8)
        Bt[(size_t)(n0 + r) * K + k0 + tx] = t[tx][r];
}

// ---- layer 0: fp32 SIMT GEMM 8192x128x1024 + bias + qrelu ----------------
__global__ __launch_bounds__(256)
void k_gemm_l0(const float* __restrict__ X, const float* __restrict__ Bq,
               const int* __restrict__ bias, uint8_t* __restrict__ Out) {
    __shared__ float As[32][65];
    __shared__ float Bs[32][64];
    int tid = threadIdx.x;
    int tx = tid & 15, ty = tid >> 4;
    int m0 = blockIdx.y * 64, n0 = blockIdx.x * 64;
    float acc[4][4] = {};
    for (int k0 = 0; k0 < 128; k0 += 32) {
        {
            int r = tid >> 3, c = tid & 7;
#pragma unroll
            for (int p = 0; p < 2; p++) {
                float4 v = *(const float4*)(X + (size_t)(m0 + r + p * 32) * 128 + k0 + c * 4);
                int rr = r + p * 32;
                As[c * 4 + 0][rr] = v.x; As[c * 4 + 1][rr] = v.y;
                As[c * 4 + 2][rr] = v.z; As[c * 4 + 3][rr] = v.w;
            }
        }
        {
            int kr = tid >> 4, cx = tid & 15;
#pragma unroll
            for (int p = 0; p < 2; p++) {
                float4 v = *(const float4*)(Bq + (size_t)(k0 + kr + p * 16) * 1024 + n0 + cx * 4);
                *(float4*)&Bs[kr + p * 16][cx * 4] = v;
            }
        }
        __syncthreads();
#pragma unroll
        for (int k = 0; k < 32; k++) {
            float a[4], b[4];
#pragma unroll
            for (int i = 0; i < 4; i++) a[i] = As[k][i * 16 + ty];
#pragma unroll
            for (int j = 0; j < 4; j++) b[j] = Bs[k][j * 16 + tx];
#pragma unroll
            for (int i = 0; i < 4; i++)
#pragma unroll
                for (int j = 0; j < 4; j++) acc[i][j] = fmaf(a[i], b[j], acc[i][j]);
        }
        __syncthreads();
    }
#pragma unroll
    for (int j = 0; j < 4; j++) {
        int n = n0 + j * 16 + tx;
        float bm2 = 2.0f * (float)bias[n];
#pragma unroll
        for (int i = 0; i < 4; i++) {
            int m = m0 + i * 16 + ty;
            float p = acc[i][j] * 64.0f + bm2;
            float q = rintf(p);
            q = fminf(fmaxf(q, 0.0f), 63.0f);
            Out[(size_t)m * 1024 + n] = (uint8_t)q;
        }
    }
}

// ---- plumbing ------------------------------------------------------------
__device__ __forceinline__ void cp16(uint32_t dst, const void* src) {
    asm volatile("cp.async.cg.shared.global [%0], [%1], 16;\n" :: "r"(dst), "l"(src));
}
__device__ __forceinline__ void cp_commit() { asm volatile("cp.async.commit_group;\n"); }
template <int N_>
__device__ __forceinline__ void cp_wait() { asm volatile("cp.async.wait_group %0;\n" :: "n"(N_)); }
__device__ __forceinline__ void ldsm4(uint32_t& r0, uint32_t& r1, uint32_t& r2, uint32_t& r3,
                                      uint32_t addr) {
    asm volatile("ldmatrix.sync.aligned.m8n8.x4.shared.b16 {%0,%1,%2,%3}, [%4];\n"
                 : "=r"(r0), "=r"(r1), "=r"(r2), "=r"(r3) : "r"(addr));
}
__device__ __forceinline__ void ldsm2(uint32_t& r0, uint32_t& r1, uint32_t addr) {
    asm volatile("ldmatrix.sync.aligned.m8n8.x2.shared.b16 {%0,%1}, [%2];\n"
                 : "=r"(r0), "=r"(r1) : "r"(addr));
}
__device__ __forceinline__ void imma(int* c, const uint32_t* a, const uint32_t* b) {
    asm volatile(
        "mma.sync.aligned.m16n8k32.row.col.s32.u8.s8.s32 "
        "{%0,%1,%2,%3}, {%4,%5,%6,%7}, {%8,%9}, {%0,%1,%2,%3};\n"
        : "+r"(c[0]), "+r"(c[1]), "+r"(c[2]), "+r"(c[3])
        : "r"(a[0]), "r"(a[1]), "r"(a[2]), "r"(a[3]), "r"(b[0]), "r"(b[1]));
}
__device__ __forceinline__ uint32_t swz(int r, int c) {
    return (uint32_t)(r * 64 + ((c ^ ((r >> 1) & 3)) << 4));
}
__device__ __forceinline__ int requant(int s) {
    int q = s >> 5, rr = s & 31;
    q += (rr > 16) ? 1 : ((rr == 16) ? (q & 1) : 0);
    return min(max(q, 0), 63);
}

// ---- layers 1..3: warp-specialized hybrid, 80 mma / 48 dp4a cols ----------
template <int K, bool LAST>
__global__ __launch_bounds__(256, 2)
void k_hyb(const uint8_t* __restrict__ A,    // [M][K] codes 0..63
           const int8_t* __restrict__ Bt,    // [N][K] codes -32..31
           const int* __restrict__ bq, const float* __restrict__ bf,
           uint8_t* __restrict__ Cq, float* __restrict__ Cf, int N) {
    extern __shared__ __align__(128) uint8_t dyn[];
    constexpr int S = 4;
    constexpr int OFF_BM = 8192;              // B mma: 80 rows x 64B swizzled
    constexpr int OFF_BD = 13312;             // B dp4a: 48 rows x 64B swizzled
    constexpr int STG = 16384;                // 8K + 5K + 3K
    constexpr int NK = K / 64;

    const int tid = threadIdx.x;
    const int wid = tid >> 5, lane = tid & 31;
    const int m0 = blockIdx.y * 128, n0 = blockIdx.x * 128;

    // --- loaders (all 256 threads): 4 cp16/thread/stage
    const int lr = tid >> 2, lc = tid & 3;
    const uint8_t* gA = A + (size_t)(m0 + lr) * K + lc * 16;
    const int8_t*  gB0 = Bt + (size_t)(n0 + lr) * K + lc * 16;        // rows 0..63 -> Bm
    const int8_t*  gB1 = Bt + (size_t)(n0 + lr + 64) * K + lc * 16;   // rows 64..127
    const size_t gStep = (size_t)64 * K;
    const uint32_t dA0 = swz(lr, lc), dA1 = swz(lr + 64, lc);
    const uint32_t dB0 = OFF_BM + swz(lr, lc);
    const int r2 = lr + 64;
    const uint32_t dB1 = (r2 < 80) ? (OFF_BM + swz(r2, lc))
                                   : (OFF_BD + swz(r2 - 80, lc));
    const uint32_t dynb = (uint32_t)__cvta_generic_to_shared(dyn);

    auto issue = [&](int ki) {
        uint32_t sb = dynb + (ki & (S - 1)) * STG;
        size_t go = (size_t)ki * 64;
        cp16(sb + dA0, gA + go);
        cp16(sb + dA1, gA + go + gStep);
        cp16(sb + dB0, gB0 + go);
        cp16(sb + dB1, gB1 + go);
        cp_commit();
    };
#pragma unroll
    for (int k = 0; k < S - 1; k++) issue(k);     // NK >= 16 always

    if (wid < 4) {
        // ================= mma warps: cols n0..n0+79 =================
        const int wm = wid >> 1, wn = wid & 1;    // 2x2 grid, warp tile 64x40
        const int g = lane >> 2, tig = lane & 3;
        const int rl = (lane & 7) + 8 * ((lane >> 3) & 1);
        const int ch = (lane >> 4) & 1;
        const int r2l = lane & 7;                 // ldsm2 rows
        const int ch2 = (lane >> 3) & 1;          // ldsm2 chunk select
        int accT[4][5][4] = {};

        for (int ki = 0; ki < NK; ki++) {
            cp_wait<S - 2>();
            __syncthreads();
            if (ki + S - 1 < NK) issue(ki + S - 1); else cp_commit();
            uint32_t sb = dynb + (ki & (S - 1)) * STG;
#pragma unroll
            for (int half = 0; half < 2; half++) {
                uint32_t b[5][2];
#pragma unroll
                for (int np = 0; np < 2; np++) {
                    uint32_t r0, r1, r2_, r3;
                    ldsm4(r0, r1, r2_, r3,
                          sb + OFF_BM + swz(wn * 40 + np * 16 + rl, 2 * half + ch));
                    b[2 * np + 0][0] = r0; b[2 * np + 0][1] = r2_;
                    b[2 * np + 1][0] = r1; b[2 * np + 1][1] = r3;
                }
                ldsm2(b[4][0], b[4][1],
                      sb + OFF_BM + swz(wn * 40 + 32 + r2l, 2 * half + ch2));
#pragma unroll
                for (int mi = 0; mi < 4; mi++) {
                    uint32_t a[4];
                    ldsm4(a[0], a[1], a[2], a[3],
                          sb + swz(wm * 64 + mi * 16 + rl, 2 * half + ch));
#pragma unroll
                    for (int nj = 0; nj < 5; nj++)
                        imma(accT[mi][nj], a, b[nj]);
                }
            }
        }
        // epilogue
#pragma unroll
        for (int nj = 0; nj < 5; nj++) {
            int n = n0 + wn * 40 + nj * 8 + 2 * tig;
            if (!LAST) {
                int mb0 = bq[n] * 64, mb1 = bq[n + 1] * 64;
#pragma unroll
                for (int mi = 0; mi < 4; mi++)
#pragma unroll
                    for (int h = 0; h < 2; h++) {
                        int m = m0 + wm * 64 + mi * 16 + g + 8 * h;
                        int q0 = requant(accT[mi][nj][2 * h + 0] + mb0);
                        int q1 = requant(accT[mi][nj][2 * h + 1] + mb1);
                        *(uint16_t*)&Cq[(size_t)m * N + n] = (uint16_t)(q0 | (q1 << 8));
                    }
            } else {
                float bb0 = bf[n], bb1 = bf[n + 1];
#pragma unroll
                for (int mi = 0; mi < 4; mi++)
#pragma unroll
                    for (int h = 0; h < 2; h++) {
                        int m = m0 + wm * 64 + mi * 16 + g + 8 * h;
                        float2 v;
                        v.x = (float)accT[mi][nj][2 * h + 0] * (1.0f / 2048.0f) + bb0;
                        v.y = (float)accT[mi][nj][2 * h + 1] * (1.0f / 2048.0f) + bb1;
                        *(float2*)&Cf[(size_t)m * N + n] = v;
                    }
            }
        }
    } else {
        // ================= dp4a warps: cols n0+80..n0+127 =================
        const int d  = tid - 128;          // 0..127
        const int ry = d & 15;             // rows ry + 16*i
        const int cg = d >> 4;             // col group 0..7: cols 80 + cg*6 + j
        const uint32_t aXor = (uint32_t)((ry >> 1) & 3);
        int accD[8][6] = {};

        for (int ki = 0; ki < NK; ki++) {
            cp_wait<S - 2>();
            __syncthreads();
            if (ki + S - 1 < NK) issue(ki + S - 1); else cp_commit();
            const uint8_t* sp = dyn + (ki & (S - 1)) * STG;
#pragma unroll
            for (int ck = 0; ck < 4; ck++) {
                uint32_t cb = ((uint32_t)ck ^ aXor) << 4;
#pragma unroll
                for (int u = 0; u < 2; u++) {
                    uint2 bv[6];
#pragma unroll
                    for (int j = 0; j < 6; j++)
                        bv[j] = *(const uint2*)(sp + OFF_BD + swz(cg * 6 + j, ck) + 8 * u);
#pragma unroll
                    for (int i = 0; i < 8; i++) {
                        uint2 av = *(const uint2*)(sp + (ry + 16 * i) * 64 + cb + 8 * u);
#pragma unroll
                        for (int j = 0; j < 6; j++) {
                            accD[i][j] = __dp4a((int)av.x, (int)bv[j].x, accD[i][j]);
                            accD[i][j] = __dp4a((int)av.y, (int)bv[j].y, accD[i][j]);
                        }
                    }
                }
            }
        }
        // epilogue: rows m0+ry+16i, cols n0+80+cg*6..+5
        const int ncol = n0 + 80 + cg * 6;
        if (!LAST) {
            int mb[6];
#pragma unroll
            for (int j = 0; j < 6; j++) mb[j] = bq[ncol + j] * 64;
#pragma unroll
            for (int i = 0; i < 8; i++) {
                int m = m0 + ry + 16 * i;
#pragma unroll
                for (int jp = 0; jp < 3; jp++) {
                    int q0 = requant(accD[i][2 * jp + 0] + mb[2 * jp + 0]);
                    int q1 = requant(accD[i][2 * jp + 1] + mb[2 * jp + 1]);
                    *(uint16_t*)&Cq[(size_t)m * N + ncol + 2 * jp] =
                        (uint16_t)(q0 | (q1 << 8));
                }
            }
        } else {
            float bb[6];
#pragma unroll
            for (int j = 0; j < 6; j++) bb[j] = bf[ncol + j];
#pragma unroll
            for (int i = 0; i < 8; i++) {
                int m = m0 + ry + 16 * i;
#pragma unroll
                for (int jp = 0; jp < 3; jp++) {
                    float2 v;
                    v.x = (float)accD[i][2 * jp + 0] * (1.0f / 2048.0f) + bb[2 * jp + 0];
                    v.y = (float)accD[i][2 * jp + 1] * (1.0f / 2048.0f) + bb[2 * jp + 1];
                    *(float2*)&Cf[(size_t)m * N + ncol + 2 * jp] = v;
                }
            }
        }
    }
}

// ---- launch --------------------------------------------------------------
extern "C" void kernel_launch(void* const* d_in, const int* in_sizes, int n_in,
                              void* d_out, int out_size) {
    const float* x  = (const float*)d_in[0];
    const float* W0 = (const float*)d_in[1]; const float* b0 = (const float*)d_in[2];
    const float* W1 = (const float*)d_in[3]; const float* b1 = (const float*)d_in[4];
    const float* W2 = (const float*)d_in[5]; const float* b2 = (const float*)d_in[6];
    const float* W3 = (const float*)d_in[7]; const float* b3 = (const float*)d_in[8];

    float *w0q, *b3q; int8_t *w1t, *w2t, *w3t; int *b0q, *b1q, *b2q;
    uint8_t *a0, *a1, *a2;
    cudaGetSymbolAddress((void**)&w0q, g_w0q);
    cudaGetSymbolAddress((void**)&w1t, g_w1t);
    cudaGetSymbolAddress((void**)&w2t, g_w2t);
    cudaGetSymbolAddress((void**)&w3t, g_w3t);
    cudaGetSymbolAddress((void**)&b0q, g_b0q);
    cudaGetSymbolAddress((void**)&b1q, g_b1q);
    cudaGetSymbolAddress((void**)&b2q, g_b2q);
    cudaGetSymbolAddress((void**)&b3q, g_b3q);
    cudaGetSymbolAddress((void**)&a0,  g_a0);
    cudaGetSymbolAddress((void**)&a1,  g_a1);
    cudaGetSymbolAddress((void**)&a2,  g_a2);

    const int SMEM = 4 * 16384;   // 65536 (2 CTAs/SM)
    cudaFuncSetAttribute(k_hyb<1024, false>, cudaFuncAttributeMaxDynamicSharedMemorySize, SMEM);
    cudaFuncSetAttribute(k_hyb<2048, false>, cudaFuncAttributeMaxDynamicSharedMemorySize, SMEM);
    cudaFuncSetAttribute(k_hyb<4096, true >, cudaFuncAttributeMaxDynamicSharedMemorySize, SMEM);

    k_quant_small<<<556, 256>>>(W0, w0q, b0, b0q, b1, b1q, b2, b2q, b3, b3q);
    k_quant_wT_all<<<26624, dim3(32, 8)>>>(W1, w1t, W2, w2t, W3, w3t);
    k_gemm_l0<<<dim3(1024 / 64, M / 64), 256>>>(x, w0q, b0q, a0);

    k_hyb<1024, false><<<dim3(2048 / 128, M / 128), 256, SMEM>>>(a0, w1t, b1q, nullptr, a1, nullptr, 2048);
    k_hyb<2048, false><<<dim3(4096 / 128, M / 128), 256, SMEM>>>(a1, w2t, b2q, nullptr, a2, nullptr, 4096);
    k_hyb<4096, true ><<<dim3(4096 / 128, M / 128), 256, SMEM>>>(a2, w3t, nullptr, b3q, nullptr, (float*)d_out, 4096);
}

// round 15
// speedup vs baseline: 1.7573x; 1.7573x over previous
#include <cuda_runtime.h>
#include <cstdint>

// ============================================================================
// VAE_Decoder_6030134084248 : 4-layer QKeras-quantized MLP (exact-integer form)
// Warp-specialized hybrid GEMM (mma.sync 64 cols / dp4a 64 cols) on a 64x128
// CTA tile with 3 CTAs/SM (<=85 regs/thread) to attack the latency limit
// seen at 16 warps/SM. r10's full-ILP fragment loading preserved.
// ============================================================================

static const int M = 8192;

// ---- scratch (device globals: no allocation allowed) ----
__device__ __align__(128) float   g_w0q[128 * 1024];
__device__ __align__(128) int8_t  g_w1t[2048l * 1024];   // [N][K] signed codes
__device__ __align__(128) int8_t  g_w2t[4096l * 2048];
__device__ __align__(128) int8_t  g_w3t[4096l * 4096];
__device__ int     g_b0q[1024];
__device__ int     g_b1q[2048];
__device__ int     g_b2q[4096];
__device__ float   g_b3q[4096];
__device__ __align__(128) uint8_t g_a0[8192l * 1024];
__device__ __align__(128) uint8_t g_a1[8192l * 2048];
__device__ __align__(128) uint8_t g_a2[8192l * 4096];

__device__ __forceinline__ float qcode(float x) {
    float c = rintf(x * 32.0f);
    return fminf(fmaxf(c, -32.0f), 31.0f);
}

// ---- fused small quantizers (1 launch) -----------------------------------
__global__ void k_quant_small(const float* __restrict__ W0, float* __restrict__ w0q,
                              const float* __restrict__ b0, int* __restrict__ b0q,
                              const float* __restrict__ b1, int* __restrict__ b1q,
                              const float* __restrict__ b2, int* __restrict__ b2q,
                              const float* __restrict__ b3, float* __restrict__ b3q) {
    int b = blockIdx.x, t = threadIdx.x;
    if (b < 512)      { int i = b * 256 + t;        w0q[i] = qcode(W0[i]) * (1.0f / 32.0f); }
    else if (b < 516) { int i = (b - 512) * 256 + t; b0q[i] = (int)qcode(b0[i]); }
    else if (b < 524) { int i = (b - 516) * 256 + t; b1q[i] = (int)qcode(b1[i]); }
    else if (b < 540) { int i = (b - 524) * 256 + t; b2q[i] = (int)qcode(b2[i]); }
    else              { int i = (b - 540) * 256 + t; b3q[i] = qcode(b3[i]) * (1.0f / 32.0f); }
}

// ---- fused transpose-quant for W1/W2/W3 (1 launch) -----------------------
__global__ void k_quant_wT_all(const float* __restrict__ W1, int8_t* __restrict__ B1,
                               const float* __restrict__ W2, int8_t* __restrict__ B2,
                               const float* __restrict__ W3, int8_t* __restrict__ B3) {
    __shared__ int8_t t[32][33];
    int b = blockIdx.x;
    const float* W; int8_t* Bt; int K, N;
    if (b < 2048)       { W = W1; Bt = B1; K = 1024; N = 2048; }
    else if (b < 10240) { b -= 2048;  W = W2; Bt = B2; K = 2048; N = 4096; }
    else                { b -= 10240; W = W3; Bt = B3; K = 4096; N = 4096; }
    int nb = N / 32;
    int n0 = (b % nb) * 32, k0 = (b / nb) * 32;
    int tx = threadIdx.x, ty = threadIdx.y;   // 32 x 8
#pragma unroll
    for (int r = ty; r < 32; r += 8)
        t[r][tx] = (int8_t)qcode(W[(size_t)(k0 + r) * N + n0 + tx]);
    __syncthreads();
#pragma unroll
    for (int r = ty; r < 32; r += 8)
        Bt[(size_t)(n0 + r) * K + k0 + tx] = t[tx][r];
}

// ---- layer 0: fp32 SIMT GEMM 8192x128x1024 + bias + qrelu ----------------
__global__ __launch_bounds__(256)
void k_gemm_l0(const float* __restrict__ X, const float* __restrict__ Bq,
               const int* __restrict__ bias, uint8_t* __restrict__ Out) {
    __shared__ float As[32][65];
    __shared__ float Bs[32][64];
    int tid = threadIdx.x;
    int tx = tid & 15, ty = tid >> 4;
    int m0 = blockIdx.y * 64, n0 = blockIdx.x * 64;
    float acc[4][4] = {};
    for (int k0 = 0; k0 < 128; k0 += 32) {
        {
            int r = tid >> 3, c = tid & 7;
#pragma unroll
            for (int p = 0; p < 2; p++) {
                float4 v = *(const float4*)(X + (size_t)(m0 + r + p * 32) * 128 + k0 + c * 4);
                int rr = r + p * 32;
                As[c * 4 + 0][rr] = v.x; As[c * 4 + 1][rr] = v.y;
                As[c * 4 + 2][rr] = v.z; As[c * 4 + 3][rr] = v.w;
            }
        }
        {
            int kr = tid >> 4, cx = tid & 15;
#pragma unroll
            for (int p = 0; p < 2; p++) {
                float4 v = *(const float4*)(Bq + (size_t)(k0 + kr + p * 16) * 1024 + n0 + cx * 4);
                *(float4*)&Bs[kr + p * 16][cx * 4] = v;
            }
        }
        __syncthreads();
#pragma unroll
        for (int k = 0; k < 32; k++) {
            float a[4], b[4];
#pragma unroll
            for (int i = 0; i < 4; i++) a[i] = As[k][i * 16 + ty];
#pragma unroll
            for (int j = 0; j < 4; j++) b[j] = Bs[k][j * 16 + tx];
#pragma unroll
            for (int i = 0; i < 4; i++)
#pragma unroll
                for (int j = 0; j < 4; j++) acc[i][j] = fmaf(a[i], b[j], acc[i][j]);
        }
        __syncthreads();
    }
#pragma unroll
    for (int j = 0; j < 4; j++) {
        int n = n0 + j * 16 + tx;
        float bm2 = 2.0f * (float)bias[n];
#pragma unroll
        for (int i = 0; i < 4; i++) {
            int m = m0 + i * 16 + ty;
            float p = acc[i][j] * 64.0f + bm2;
            float q = rintf(p);
            q = fminf(fmaxf(q, 0.0f), 63.0f);
            Out[(size_t)m * 1024 + n] = (uint8_t)q;
        }
    }
}

// ---- plumbing ------------------------------------------------------------
__device__ __forceinline__ void cp16(uint32_t dst, const void* src) {
    asm volatile("cp.async.cg.shared.global [%0], [%1], 16;\n" :: "r"(dst), "l"(src));
}
__device__ __forceinline__ void cp_commit() { asm volatile("cp.async.commit_group;\n"); }
template <int N_>
__device__ __forceinline__ void cp_wait() { asm volatile("cp.async.wait_group %0;\n" :: "n"(N_)); }
__device__ __forceinline__ void ldsm4(uint32_t& r0, uint32_t& r1, uint32_t& r2, uint32_t& r3,
                                      uint32_t addr) {
    asm volatile("ldmatrix.sync.aligned.m8n8.x4.shared.b16 {%0,%1,%2,%3}, [%4];\n"
                 : "=r"(r0), "=r"(r1), "=r"(r2), "=r"(r3) : "r"(addr));
}
__device__ __forceinline__ void imma(int* c, const uint32_t* a, const uint32_t* b) {
    asm volatile(
        "mma.sync.aligned.m16n8k32.row.col.s32.u8.s8.s32 "
        "{%0,%1,%2,%3}, {%4,%5,%6,%7}, {%8,%9}, {%0,%1,%2,%3};\n"
        : "+r"(c[0]), "+r"(c[1]), "+r"(c[2]), "+r"(c[3])
        : "r"(a[0]), "r"(a[1]), "r"(a[2]), "r"(a[3]), "r"(b[0]), "r"(b[1]));
}
__device__ __forceinline__ uint32_t swz(int r, int c) {
    return (uint32_t)(r * 64 + ((c ^ ((r >> 1) & 3)) << 4));
}
__device__ __forceinline__ int requant(int s) {
    int q = s >> 5, rr = s & 31;
    q += (rr > 16) ? 1 : ((rr == 16) ? (q & 1) : 0);
    return min(max(q, 0), 63);
}

// ---- layers 1..3: warp-specialized hybrid, 64x128 tile, 3 CTAs/SM ---------
// warps 0-3: mma.sync cols 0..63 (32x32 warp tiles, 2x2 grid)
// warps 4-7: dp4a cols 64..127 (4 rows x 8 cols per thread)
template <int K, bool LAST>
__global__ __launch_bounds__(256, 3)
void k_hyb(const uint8_t* __restrict__ A,    // [M][K] codes 0..63
           const int8_t* __restrict__ Bt,    // [N][K] codes -32..31
           const int* __restrict__ bq, const float* __restrict__ bf,
           uint8_t* __restrict__ Cq, float* __restrict__ Cf, int N) {
    extern __shared__ __align__(128) uint8_t dyn[];
    constexpr int S = 4;
    constexpr int OFF_BM = 4096;              // B mma: 64 rows x 64B swizzled
    constexpr int OFF_BD = 8192;              // B dp4a: 64 rows x 64B swizzled
    constexpr int STG = 12288;
    constexpr int NK = K / 64;

    const int tid = threadIdx.x;
    const int wid = tid >> 5, lane = tid & 31;
    const int m0 = blockIdx.y * 64, n0 = blockIdx.x * 128;

    // --- loaders (all 256 threads): 3 cp16/thread/stage
    const int lr = tid >> 2, lc = tid & 3;
    const uint8_t* gA  = A  + (size_t)(m0 + lr) * K + lc * 16;
    const int8_t*  gBm = Bt + (size_t)(n0 + lr) * K + lc * 16;
    const int8_t*  gBd = Bt + (size_t)(n0 + 64 + lr) * K + lc * 16;
    const uint32_t dA0 = swz(lr, lc);
    const uint32_t dynb = (uint32_t)__cvta_generic_to_shared(dyn);

    auto issue = [&](int ki) {
        uint32_t sb = dynb + (ki & (S - 1)) * STG;
        size_t go = (size_t)ki * 64;
        cp16(sb + dA0, gA + go);
        cp16(sb + OFF_BM + dA0, gBm + go);
        cp16(sb + OFF_BD + dA0, gBd + go);
        cp_commit();
    };
#pragma unroll
    for (int k = 0; k < S - 1; k++) issue(k);     // NK >= 16 always

    if (wid < 4) {
        // ================= mma warps: cols n0..n0+63 =================
        const int wm = wid >> 1, wn = wid & 1;    // 2x2 grid, warp tile 32x32
        const int g = lane >> 2, tig = lane & 3;
        const int rl = (lane & 7) + 8 * ((lane >> 3) & 1);
        const int ch = (lane >> 4) & 1;
        int accT[2][4][4] = {};

        for (int ki = 0; ki < NK; ki++) {
            cp_wait<S - 2>();
            __syncthreads();
            if (ki + S - 1 < NK) issue(ki + S - 1); else cp_commit();
            uint32_t sb = dynb + (ki & (S - 1)) * STG;
#pragma unroll
            for (int half = 0; half < 2; half++) {
                uint32_t a[2][4], b[4][2];
#pragma unroll
                for (int mi = 0; mi < 2; mi++)
                    ldsm4(a[mi][0], a[mi][1], a[mi][2], a[mi][3],
                          sb + swz(wm * 32 + mi * 16 + rl, 2 * half + ch));
#pragma unroll
                for (int np = 0; np < 2; np++) {
                    uint32_t r0, r1, r2, r3;
                    ldsm4(r0, r1, r2, r3,
                          sb + OFF_BM + swz(wn * 32 + np * 16 + rl, 2 * half + ch));
                    b[2 * np + 0][0] = r0; b[2 * np + 0][1] = r2;
                    b[2 * np + 1][0] = r1; b[2 * np + 1][1] = r3;
                }
#pragma unroll
                for (int mi = 0; mi < 2; mi++)
#pragma unroll
                    for (int nj = 0; nj < 4; nj++)
                        imma(accT[mi][nj], a[mi], b[nj]);
            }
        }
        // epilogue
#pragma unroll
        for (int nj = 0; nj < 4; nj++) {
            int n = n0 + wn * 32 + nj * 8 + 2 * tig;
            if (!LAST) {
                int mb0 = bq[n] * 64, mb1 = bq[n + 1] * 64;
#pragma unroll
                for (int mi = 0; mi < 2; mi++)
#pragma unroll
                    for (int h = 0; h < 2; h++) {
                        int m = m0 + wm * 32 + mi * 16 + g + 8 * h;
                        int q0 = requant(accT[mi][nj][2 * h + 0] + mb0);
                        int q1 = requant(accT[mi][nj][2 * h + 1] + mb1);
                        *(uint16_t*)&Cq[(size_t)m * N + n] = (uint16_t)(q0 | (q1 << 8));
                    }
            } else {
                float bb0 = bf[n], bb1 = bf[n + 1];
#pragma unroll
                for (int mi = 0; mi < 2; mi++)
#pragma unroll
                    for (int h = 0; h < 2; h++) {
                        int m = m0 + wm * 32 + mi * 16 + g + 8 * h;
                        float2 v;
                        v.x = (float)accT[mi][nj][2 * h + 0] * (1.0f / 2048.0f) + bb0;
                        v.y = (float)accT[mi][nj][2 * h + 1] * (1.0f / 2048.0f) + bb1;
                        *(float2*)&Cf[(size_t)m * N + n] = v;
                    }
            }
        }
    } else {
        // ================= dp4a warps: cols n0+64..n0+127 =================
        const int d  = tid - 128;          // 0..127
        const int ry = d & 15;             // rows ry + 16*i, i in 0..3
        const int cg = d >> 4;             // col group: cols 64 + cg*8 + j
        const uint32_t aXor = (uint32_t)((ry >> 1) & 3);
        int accD[4][8] = {};

        for (int ki = 0; ki < NK; ki++) {
            cp_wait<S - 2>();
            __syncthreads();
            if (ki + S - 1 < NK) issue(ki + S - 1); else cp_commit();
            const uint8_t* sp = dyn + (ki & (S - 1)) * STG;
#pragma unroll
            for (int ck = 0; ck < 4; ck++) {
                uint32_t cb = ((uint32_t)ck ^ aXor) << 4;
#pragma unroll
                for (int u = 0; u < 2; u++) {
                    uint2 bv[8];
#pragma unroll
                    for (int j = 0; j < 8; j++)
                        bv[j] = *(const uint2*)(sp + OFF_BD + swz(cg * 8 + j, ck) + 8 * u);
#pragma unroll
                    for (int i = 0; i < 4; i++) {
                        uint2 av = *(const uint2*)(sp + (ry + 16 * i) * 64 + cb + 8 * u);
#pragma unroll
                        for (int j = 0; j < 8; j++) {
                            accD[i][j] = __dp4a((int)av.x, (int)bv[j].x, accD[i][j]);
                            accD[i][j] = __dp4a((int)av.y, (int)bv[j].y, accD[i][j]);
                        }
                    }
                }
            }
        }
        // epilogue: rows m0+ry+16i, cols n0+64+cg*8..+7
        const int ncol = n0 + 64 + cg * 8;
        if (!LAST) {
            int mb[8];
#pragma unroll
            for (int j = 0; j < 8; j++) mb[j] = bq[ncol + j] * 64;
#pragma unroll
            for (int i = 0; i < 4; i++) {
                int m = m0 + ry + 16 * i;
                uint32_t lo = 0, hi = 0;
#pragma unroll
                for (int j = 0; j < 4; j++) {
                    lo |= (uint32_t)requant(accD[i][j] + mb[j]) << (8 * j);
                    hi |= (uint32_t)requant(accD[i][4 + j] + mb[4 + j]) << (8 * j);
                }
                *(uint2*)&Cq[(size_t)m * N + ncol] = make_uint2(lo, hi);
            }
        } else {
            float bb[8];
#pragma unroll
            for (int j = 0; j < 8; j++) bb[j] = bf[ncol + j];
#pragma unroll
            for (int i = 0; i < 4; i++) {
                int m = m0 + ry + 16 * i;
                float4 v0, v1;
                v0.x = (float)accD[i][0] * (1.0f / 2048.0f) + bb[0];
                v0.y = (float)accD[i][1] * (1.0f / 2048.0f) + bb[1];
                v0.z = (float)accD[i][2] * (1.0f / 2048.0f) + bb[2];
                v0.w = (float)accD[i][3] * (1.0f / 2048.0f) + bb[3];
                v1.x = (float)accD[i][4] * (1.0f / 2048.0f) + bb[4];
                v1.y = (float)accD[i][5] * (1.0f / 2048.0f) + bb[5];
                v1.z = (float)accD[i][6] * (1.0f / 2048.0f) + bb[6];
                v1.w = (float)accD[i][7] * (1.0f / 2048.0f) + bb[7];
                *(float4*)&Cf[(size_t)m * N + ncol] = v0;
                *(float4*)&Cf[(size_t)m * N + ncol + 4] = v1;
            }
        }
    }
}

// ---- launch --------------------------------------------------------------
extern "C" void kernel_launch(void* const* d_in, const int* in_sizes, int n_in,
                              void* d_out, int out_size) {
    const float* x  = (const float*)d_in[0];
    const float* W0 = (const float*)d_in[1]; const float* b0 = (const float*)d_in[2];
    const float* W1 = (const float*)d_in[3]; const float* b1 = (const float*)d_in[4];
    const float* W2 = (const float*)d_in[5]; const float* b2 = (const float*)d_in[6];
    const float* W3 = (const float*)d_in[7]; const float* b3 = (const float*)d_in[8];

    float *w0q, *b3q; int8_t *w1t, *w2t, *w3t; int *b0q, *b1q, *b2q;
    uint8_t *a0, *a1, *a2;
    cudaGetSymbolAddress((void**)&w0q, g_w0q);
    cudaGetSymbolAddress((void**)&w1t, g_w1t);
    cudaGetSymbolAddress((void**)&w2t, g_w2t);
    cudaGetSymbolAddress((void**)&w3t, g_w3t);
    cudaGetSymbolAddress((void**)&b0q, g_b0q);
    cudaGetSymbolAddress((void**)&b1q, g_b1q);
    cudaGetSymbolAddress((void**)&b2q, g_b2q);
    cudaGetSymbolAddress((void**)&b3q, g_b3q);
    cudaGetSymbolAddress((void**)&a0,  g_a0);
    cudaGetSymbolAddress((void**)&a1,  g_a1);
    cudaGetSymbolAddress((void**)&a2,  g_a2);

    const int SMEM = 4 * 12288;   // 49152 (3 CTAs/SM: 144KB <= 228KB)
    cudaFuncSetAttribute(k_hyb<1024, false>, cudaFuncAttributeMaxDynamicSharedMemorySize, SMEM);
    cudaFuncSetAttribute(k_hyb<2048, false>, cudaFuncAttributeMaxDynamicSharedMemorySize, SMEM);
    cudaFuncSetAttribute(k_hyb<4096, true >, cudaFuncAttributeMaxDynamicSharedMemorySize, SMEM);

    k_quant_small<<<556, 256>>>(W0, w0q, b0, b0q, b1, b1q, b2, b2q, b3, b3q);
    k_quant_wT_all<<<26624, dim3(32, 8)>>>(W1, w1t, W2, w2t, W3, w3t);
    k_gemm_l0<<<dim3(1024 / 64, M / 64), 256>>>(x, w0q, b0q, a0);

    k_hyb<1024, false><<<dim3(2048 / 128, M / 64), 256, SMEM>>>(a0, w1t, b1q, nullptr, a1, nullptr, 2048);
    k_hyb<2048, false><<<dim3(4096 / 128, M / 64), 256, SMEM>>>(a1, w2t, b2q, nullptr, a2, nullptr, 4096);
    k_hyb<4096, true ><<<dim3(4096 / 128, M / 64), 256, SMEM>>>(a2, w3t, nullptr, b3q, nullptr, (float*)d_out, 4096);
}

// round 17
// speedup vs baseline: 1.8784x; 1.0689x over previous
#include <cuda_runtime.h>
#include <cstdint>

// ============================================================================
// VAE_Decoder_6030134084248 : 4-layer QKeras-quantized MLP (exact-integer form)
// Warp-specialized hybrid GEMM, 64x128 CTA tile, 3 CTAs/SM.
// warps 0-3: mma.sync cols 0..63 + ALL cp.async loading (issue-light side)
// warps 4-7: dp4a cols 64..127, pure compute, LDS.128 staged reads.
// ============================================================================

static const int M = 8192;

// ---- scratch (device globals: no allocation allowed) ----
__device__ __align__(128) float   g_w0q[128 * 1024];
__device__ __align__(128) int8_t  g_w1t[2048l * 1024];   // [N][K] signed codes
__device__ __align__(128) int8_t  g_w2t[4096l * 2048];
__device__ __align__(128) int8_t  g_w3t[4096l * 4096];
__device__ int     g_b0q[1024];
__device__ int     g_b1q[2048];
__device__ int     g_b2q[4096];
__device__ float   g_b3q[4096];
__device__ __align__(128) uint8_t g_a0[8192l * 1024];
__device__ __align__(128) uint8_t g_a1[8192l * 2048];
__device__ __align__(128) uint8_t g_a2[8192l * 4096];

__device__ __forceinline__ float qcode(float x) {
    float c = rintf(x * 32.0f);
    return fminf(fmaxf(c, -32.0f), 31.0f);
}

// ---- fused small quantizers (1 launch) -----------------------------------
__global__ void k_quant_small(const float* __restrict__ W0, float* __restrict__ w0q,
                              const float* __restrict__ b0, int* __restrict__ b0q,
                              const float* __restrict__ b1, int* __restrict__ b1q,
                              const float* __restrict__ b2, int* __restrict__ b2q,
                              const float* __restrict__ b3, float* __restrict__ b3q) {
    int b = blockIdx.x, t = threadIdx.x;
    if (b < 512)      { int i = b * 256 + t;        w0q[i] = qcode(W0[i]) * (1.0f / 32.0f); }
    else if (b < 516) { int i = (b - 512) * 256 + t; b0q[i] = (int)qcode(b0[i]); }
    else if (b < 524) { int i = (b - 516) * 256 + t; b1q[i] = (int)qcode(b1[i]); }
    else if (b < 540) { int i = (b - 524) * 256 + t; b2q[i] = (int)qcode(b2[i]); }
    else              { int i = (b - 540) * 256 + t; b3q[i] = qcode(b3[i]) * (1.0f / 32.0f); }
}

// ---- fused transpose-quant for W1/W2/W3 (1 launch) -----------------------
__global__ void k_quant_wT_all(const float* __restrict__ W1, int8_t* __restrict__ B1,
                               const float* __restrict__ W2, int8_t* __restrict__ B2,
                               const float* __restrict__ W3, int8_t* __restrict__ B3) {
    __shared__ int8_t t[32][33];
    int b = blockIdx.x;
    const float* W; int8_t* Bt; int K, N;
    if (b < 2048)       { W = W1; Bt = B1; K = 1024; N = 2048; }
    else if (b < 10240) { b -= 2048;  W = W2; Bt = B2; K = 2048; N = 4096; }
    else                { b -= 10240; W = W3; Bt = B3; K = 4096; N = 4096; }
    int nb = N / 32;
    int n0 = (b % nb) * 32, k0 = (b / nb) * 32;
    int tx = threadIdx.x, ty = threadIdx.y;   // 32 x 8
#pragma unroll
    for (int r = ty; r < 32; r += 8)
        t[r][tx] = (int8_t)qcode(W[(size_t)(k0 + r) * N + n0 + tx]);
    __syncthreads();
#pragma unroll
    for (int r = ty; r < 32; r += 8)
        Bt[(size_t)(n0 + r) * K + k0 + tx] = t[tx][r];
}

// ---- layer 0: fp32 SIMT GEMM 8192x128x1024 + bias + qrelu ----------------
__global__ __launch_bounds__(256)
void k_gemm_l0(const float* __restrict__ X, const float* __restrict__ Bq,
               const int* __restrict__ bias, uint8_t* __restrict__ Out) {
    __shared__ float As[32][65];
    __shared__ float Bs[32][64];
    int tid = threadIdx.x;
    int tx = tid & 15, ty = tid >> 4;
    int m0 = blockIdx.y * 64, n0 = blockIdx.x * 64;
    float acc[4][4] = {};
    for (int k0 = 0; k0 < 128; k0 += 32) {
        {
            int r = tid >> 3, c = tid & 7;
#pragma unroll
            for (int p = 0; p < 2; p++) {
                float4 v = *(const float4*)(X + (size_t)(m0 + r + p * 32) * 128 + k0 + c * 4);
                int rr = r + p * 32;
                As[c * 4 + 0][rr] = v.x; As[c * 4 + 1][rr] = v.y;
                As[c * 4 + 2][rr] = v.z; As[c * 4 + 3][rr] = v.w;
            }
        }
        {
            int kr = tid >> 4, cx = tid & 15;
#pragma unroll
            for (int p = 0; p < 2; p++) {
                float4 v = *(const float4*)(Bq + (size_t)(k0 + kr + p * 16) * 1024 + n0 + cx * 4);
                *(float4*)&Bs[kr + p * 16][cx * 4] = v;
            }
        }
        __syncthreads();
#pragma unroll
        for (int k = 0; k < 32; k++) {
            float a[4], b[4];
#pragma unroll
            for (int i = 0; i < 4; i++) a[i] = As[k][i * 16 + ty];
#pragma unroll
            for (int j = 0; j < 4; j++) b[j] = Bs[k][j * 16 + tx];
#pragma unroll
            for (int i = 0; i < 4; i++)
#pragma unroll
                for (int j = 0; j < 4; j++) acc[i][j] = fmaf(a[i], b[j], acc[i][j]);
        }
        __syncthreads();
    }
#pragma unroll
    for (int j = 0; j < 4; j++) {
        int n = n0 + j * 16 + tx;
        float bm2 = 2.0f * (float)bias[n];
#pragma unroll
        for (int i = 0; i < 4; i++) {
            int m = m0 + i * 16 + ty;
            float p = acc[i][j] * 64.0f + bm2;
            float q = rintf(p);
            q = fminf(fmaxf(q, 0.0f), 63.0f);
            Out[(size_t)m * 1024 + n] = (uint8_t)q;
        }
    }
}

// ---- plumbing ------------------------------------------------------------
__device__ __forceinline__ void cp16(uint32_t dst, const void* src) {
    asm volatile("cp.async.cg.shared.global [%0], [%1], 16;\n" :: "r"(dst), "l"(src));
}
__device__ __forceinline__ void cp_commit() { asm volatile("cp.async.commit_group;\n"); }
template <int N_>
__device__ __forceinline__ void cp_wait() { asm volatile("cp.async.wait_group %0;\n" :: "n"(N_)); }
__device__ __forceinline__ void ldsm4(uint32_t& r0, uint32_t& r1, uint32_t& r2, uint32_t& r3,
                                      uint32_t addr) {
    asm volatile("ldmatrix.sync.aligned.m8n8.x4.shared.b16 {%0,%1,%2,%3}, [%4];\n"
                 : "=r"(r0), "=r"(r1), "=r"(r2), "=r"(r3) : "r"(addr));
}
__device__ __forceinline__ void imma(int* c, const uint32_t* a, const uint32_t* b) {
    asm volatile(
        "mma.sync.aligned.m16n8k32.row.col.s32.u8.s8.s32 "
        "{%0,%1,%2,%3}, {%4,%5,%6,%7}, {%8,%9}, {%0,%1,%2,%3};\n"
        : "+r"(c[0]), "+r"(c[1]), "+r"(c[2]), "+r"(c[3])
        : "r"(a[0]), "r"(a[1]), "r"(a[2]), "r"(a[3]), "r"(b[0]), "r"(b[1]));
}
__device__ __forceinline__ uint32_t swz(int r, int c) {
    return (uint32_t)(r * 64 + ((c ^ ((r >> 1) & 3)) << 4));
}
__device__ __forceinline__ int requant(int s) {
    int q = s >> 5, rr = s & 31;
    q += (rr > 16) ? 1 : ((rr == 16) ? (q & 1) : 0);
    return min(max(q, 0), 63);
}
__device__ __forceinline__ int dp4x4(uint4 a, uint4 b, int acc) {
    acc = __dp4a((int)a.x, (int)b.x, acc);
    acc = __dp4a((int)a.y, (int)b.y, acc);
    acc = __dp4a((int)a.z, (int)b.z, acc);
    acc = __dp4a((int)a.w, (int)b.w, acc);
    return acc;
}

// ---- layers 1..3: warp-specialized hybrid, 64x128 tile, 3 CTAs/SM ---------
// warps 0-3: mma.sync cols 0..63 (32x32 warp tiles) + all cp.async loading
// warps 4-7: dp4a cols 64..127 (4 rows x 8 cols per thread), pure compute
template <int K, bool LAST>
__global__ __launch_bounds__(256, 3)
void k_hyb(const uint8_t* __restrict__ A,    // [M][K] codes 0..63
           const int8_t* __restrict__ Bt,    // [N][K] codes -32..31
           const int* __restrict__ bq, const float* __restrict__ bf,
           uint8_t* __restrict__ Cq, float* __restrict__ Cf, int N) {
    extern __shared__ __align__(128) uint8_t dyn[];
    constexpr int S = 4;
    constexpr int OFF_BM = 4096;              // B mma: 64 rows x 64B swizzled
    constexpr int OFF_BD = 8192;              // B dp4a: 64 rows x 64B swizzled
    constexpr int STG = 12288;
    constexpr int NK = K / 64;

    const int tid = threadIdx.x;
    const int wid = tid >> 5, lane = tid & 31;
    const int m0 = blockIdx.y * 64, n0 = blockIdx.x * 128;
    const uint32_t dynb = (uint32_t)__cvta_generic_to_shared(dyn);

    if (wid < 4) {
        // ======== mma warps: loading + mma on cols n0..n0+63 ========
        // loader: 128 threads x 6 cp16/stage (A 2, Bm 2, Bd 2)
        const int lr = tid >> 2, lc = tid & 3;           // row 0..31, chunk
        const uint8_t* gA  = A  + (size_t)(m0 + lr) * K + lc * 16;
        const int8_t*  gBm = Bt + (size_t)(n0 + lr) * K + lc * 16;
        const int8_t*  gBd = Bt + (size_t)(n0 + 64 + lr) * K + lc * 16;
        const size_t g32 = (size_t)32 * K;
        const uint32_t d0 = swz(lr, lc), d1 = swz(lr + 32, lc);

        auto issue = [&](int ki) {
            uint32_t sb = dynb + (ki & (S - 1)) * STG;
            size_t go = (size_t)ki * 64;
            cp16(sb + d0, gA + go);
            cp16(sb + d1, gA + go + g32);
            cp16(sb + OFF_BM + d0, gBm + go);
            cp16(sb + OFF_BM + d1, gBm + go + g32);
            cp16(sb + OFF_BD + d0, gBd + go);
            cp16(sb + OFF_BD + d1, gBd + go + g32);
            cp_commit();
        };
#pragma unroll
        for (int k = 0; k < S - 1; k++) issue(k);     // NK >= 16 always

        const int wm = wid >> 1, wn = wid & 1;        // 2x2 grid, tile 32x32
        const int g = lane >> 2, tig = lane & 3;
        const int rl = (lane & 7) + 8 * ((lane >> 3) & 1);
        const int ch = (lane >> 4) & 1;
        int accT[2][4][4] = {};

        for (int ki = 0; ki < NK; ki++) {
            cp_wait<S - 2>();
            __syncthreads();
            if (ki + S - 1 < NK) issue(ki + S - 1); else cp_commit();
            uint32_t sb = dynb + (ki & (S - 1)) * STG;
#pragma unroll
            for (int half = 0; half < 2; half++) {
                uint32_t a[2][4], b[4][2];
#pragma unroll
                for (int mi = 0; mi < 2; mi++)
                    ldsm4(a[mi][0], a[mi][1], a[mi][2], a[mi][3],
                          sb + swz(wm * 32 + mi * 16 + rl, 2 * half + ch));
#pragma unroll
                for (int np = 0; np < 2; np++) {
                    uint32_t r0, r1, r2, r3;
                    ldsm4(r0, r1, r2, r3,
                          sb + OFF_BM + swz(wn * 32 + np * 16 + rl, 2 * half + ch));
                    b[2 * np + 0][0] = r0; b[2 * np + 0][1] = r2;
                    b[2 * np + 1][0] = r1; b[2 * np + 1][1] = r3;
                }
#pragma unroll
                for (int mi = 0; mi < 2; mi++)
#pragma unroll
                    for (int nj = 0; nj < 4; nj++)
                        imma(accT[mi][nj], a[mi], b[nj]);
            }
        }
        // epilogue
#pragma unroll
        for (int nj = 0; nj < 4; nj++) {
            int n = n0 + wn * 32 + nj * 8 + 2 * tig;
            if (!LAST) {
                int mb0 = bq[n] * 64, mb1 = bq[n + 1] * 64;
#pragma unroll
                for (int mi = 0; mi < 2; mi++)
#pragma unroll
                    for (int h = 0; h < 2; h++) {
                        int m = m0 + wm * 32 + mi * 16 + g + 8 * h;
                        int q0 = requant(accT[mi][nj][2 * h + 0] + mb0);
                        int q1 = requant(accT[mi][nj][2 * h + 1] + mb1);
                        *(uint16_t*)&Cq[(size_t)m * N + n] = (uint16_t)(q0 | (q1 << 8));
                    }
            } else {
                float bb0 = bf[n], bb1 = bf[n + 1];
#pragma unroll
                for (int mi = 0; mi < 2; mi++)
#pragma unroll
                    for (int h = 0; h < 2; h++) {
                        int m = m0 + wm * 32 + mi * 16 + g + 8 * h;
                        float2 v;
                        v.x = (float)accT[mi][nj][2 * h + 0] * (1.0f / 2048.0f) + bb0;
                        v.y = (float)accT[mi][nj][2 * h + 1] * (1.0f / 2048.0f) + bb1;
                        *(float2*)&Cf[(size_t)m * N + n] = v;
                    }
            }
        }
    } else {
        // ======== dp4a warps: cols n0+64..n0+127, pure compute ========
        const int d  = tid - 128;          // 0..127
        const int ry = d & 15;             // rows ry + 16*i, i in 0..3
        const int cg = d >> 4;             // col group: cols 64 + cg*8 + j
        const uint32_t aXor = (uint32_t)((ry >> 1) & 3);
        int accD[4][8] = {};

        for (int ki = 0; ki < NK; ki++) {
            __syncthreads();               // data for stage ki guaranteed by
                                           // mma warps' cp_wait before barrier
            const uint8_t* sp = dyn + (ki & (S - 1)) * STG;
#pragma unroll
            for (int ck = 0; ck < 4; ck++) {
                uint32_t cb = ((uint32_t)ck ^ aXor) << 4;
                uint4 av4[4];
#pragma unroll
                for (int i = 0; i < 4; i++)
                    av4[i] = *(const uint4*)(sp + (ry + 16 * i) * 64 + cb);
#pragma unroll
                for (int jh = 0; jh < 2; jh++) {
                    uint4 bv4[4];
#pragma unroll
                    for (int j = 0; j < 4; j++)
                        bv4[j] = *(const uint4*)(sp + OFF_BD + swz(cg * 8 + jh * 4 + j, ck));
#pragma unroll
                    for (int i = 0; i < 4; i++)
#pragma unroll
                        for (int j = 0; j < 4; j++)
                            accD[i][jh * 4 + j] = dp4x4(av4[i], bv4[j], accD[i][jh * 4 + j]);
                }
            }
        }
        // epilogue: rows m0+ry+16i, cols n0+64+cg*8..+7
        const int ncol = n0 + 64 + cg * 8;
        if (!LAST) {
            int mb[8];
#pragma unroll
            for (int j = 0; j < 8; j++) mb[j] = bq[ncol + j] * 64;
#pragma unroll
            for (int i = 0; i < 4; i++) {
                int m = m0 + ry + 16 * i;
                uint32_t lo = 0, hi = 0;
#pragma unroll
                for (int j = 0; j < 4; j++) {
                    lo |= (uint32_t)requant(accD[i][j] + mb[j]) << (8 * j);
                    hi |= (uint32_t)requant(accD[i][4 + j] + mb[4 + j]) << (8 * j);
                }
                *(uint2*)&Cq[(size_t)m * N + ncol] = make_uint2(lo, hi);
            }
        } else {
            float bb[8];
#pragma unroll
            for (int j = 0; j < 8; j++) bb[j] = bf[ncol + j];
#pragma unroll
            for (int i = 0; i < 4; i++) {
                int m = m0 + ry + 16 * i;
                float4 v0, v1;
                v0.x = (float)accD[i][0] * (1.0f / 2048.0f) + bb[0];
                v0.y = (float)accD[i][1] * (1.0f / 2048.0f) + bb[1];
                v0.z = (float)accD[i][2] * (1.0f / 2048.0f) + bb[2];
                v0.w = (float)accD[i][3] * (1.0f / 2048.0f) + bb[3];
                v1.x = (float)accD[i][4] * (1.0f / 2048.0f) + bb[4];
                v1.y = (float)accD[i][5] * (1.0f / 2048.0f) + bb[5];
                v1.z = (float)accD[i][6] * (1.0f / 2048.0f) + bb[6];
                v1.w = (float)accD[i][7] * (1.0f / 2048.0f) + bb[7];
                *(float4*)&Cf[(size_t)m * N + ncol] = v0;
                *(float4*)&Cf[(size_t)m * N + ncol + 4] = v1;
            }
        }
    }
}

// ---- launch --------------------------------------------------------------
extern "C" void kernel_launch(void* const* d_in, const int* in_sizes, int n_in,
                              void* d_out, int out_size) {
    const float* x  = (const float*)d_in[0];
    const float* W0 = (const float*)d_in[1]; const float* b0 = (const float*)d_in[2];
    const float* W1 = (const float*)d_in[3]; const float* b1 = (const float*)d_in[4];
    const float* W2 = (const float*)d_in[5]; const float* b2 = (const float*)d_in[6];
    const float* W3 = (const float*)d_in[7]; const float* b3 = (const float*)d_in[8];

    float *w0q, *b3q; int8_t *w1t, *w2t, *w3t; int *b0q, *b1q, *b2q;
    uint8_t *a0, *a1, *a2;
    cudaGetSymbolAddress((void**)&w0q, g_w0q);
    cudaGetSymbolAddress((void**)&w1t, g_w1t);
    cudaGetSymbolAddress((void**)&w2t, g_w2t);
    cudaGetSymbolAddress((void**)&w3t, g_w3t);
    cudaGetSymbolAddress((void**)&b0q, g_b0q);
    cudaGetSymbolAddress((void**)&b1q, g_b1q);
    cudaGetSymbolAddress((void**)&b2q, g_b2q);
    cudaGetSymbolAddress((void**)&b3q, g_b3q);
    cudaGetSymbolAddress((void**)&a0,  g_a0);
    cudaGetSymbolAddress((void**)&a1,  g_a1);
    cudaGetSymbolAddress((void**)&a2,  g_a2);

    const int SMEM = 4 * 12288;   // 49152 (3 CTAs/SM: 144KB <= 228KB)
    cudaFuncSetAttribute(k_hyb<1024, false>, cudaFuncAttributeMaxDynamicSharedMemorySize, SMEM);
    cudaFuncSetAttribute(k_hyb<2048, false>, cudaFuncAttributeMaxDynamicSharedMemorySize, SMEM);
    cudaFuncSetAttribute(k_hyb<4096, true >, cudaFuncAttributeMaxDynamicSharedMemorySize, SMEM);

    k_quant_small<<<556, 256>>>(W0, w0q, b0, b0q, b1, b1q, b2, b2q, b3, b3q);
    k_quant_wT_all<<<26624, dim3(32, 8)>>>(W1, w1t, W2, w2t, W3, w3t);
    k_gemm_l0<<<dim3(1024 / 64, M / 64), 256>>>(x, w0q, b0q, a0);

    k_hyb<1024, false><<<dim3(2048 / 128, M / 64), 256, SMEM>>>(a0, w1t, b1q, nullptr, a1, nullptr, 2048);
    k_hyb<2048, false><<<dim3(4096 / 128, M / 64), 256, SMEM>>>(a1, w2t, b2q, nullptr, a2, nullptr, 4096);
    k_hyb<4096, true ><<<dim3(4096 / 128, M / 64), 256, SMEM>>>(a2, w3t, nullptr, b3q, nullptr, (float*)d_out, 4096);
}